// round 8
// baseline (speedup 1.0000x reference)
#include <cuda_runtime.h>
#include <cuda_bf16.h>
#include <cstdint>

#define N_NODES 100000
#define N_EDGES 1600000
#define NB ((N_NODES + 1023) / 1024)
#define MTILES ((N_NODES + 127) / 128)

// ======================= PTX helpers (arch-agnostic, sm_80+) ================
__device__ __forceinline__ uint32_t smem_u32(const void* p) {
    uint32_t a;
    asm("{ .reg .u64 t; cvta.to.shared.u64 t, %1; cvt.u32.u64 %0, t; }" : "=r"(a) : "l"(p));
    return a;
}
__device__ __forceinline__ void ldsm_x4(uint32_t* r, uint32_t addr) {
    asm volatile("ldmatrix.sync.aligned.m8n8.x4.shared.b16 {%0,%1,%2,%3}, [%4];"
        : "=r"(r[0]), "=r"(r[1]), "=r"(r[2]), "=r"(r[3]) : "r"(addr));
}
__device__ __forceinline__ void mma_bf16(float* c, const uint32_t* a, uint32_t b0, uint32_t b1) {
    asm volatile("mma.sync.aligned.m16n8k16.row.col.f32.bf16.bf16.f32 "
        "{%0,%1,%2,%3}, {%4,%5,%6,%7}, {%8,%9}, {%0,%1,%2,%3};"
        : "+f"(c[0]), "+f"(c[1]), "+f"(c[2]), "+f"(c[3])
        : "r"(a[0]), "r"(a[1]), "r"(a[2]), "r"(a[3]), "r"(b0), "r"(b1));
}
__device__ __forceinline__ void cp16(uint32_t dst, const void* src, int srcbytes) {
    asm volatile("cp.async.cg.shared.global [%0], [%1], 16, %2;"
                 :: "r"(dst), "l"(src), "r"(srcbytes));
}
#define CP_COMMIT() asm volatile("cp.async.commit_group;" ::: "memory")
#define CP_WAIT(n)  asm volatile("cp.async.wait_group %0;" :: "n"(n) : "memory")

// ======================= scratch globals ====================================
__device__ int g_deg[N_NODES];
__device__ int g_off[N_NODES + 1];
__device__ int g_cur[N_NODES];
__device__ int g_bsum[128];
__device__ int g_boff[128];
__device__ int g_csr[N_EDGES];

__device__ __nv_bfloat16 g_xhi[(size_t)N_NODES * 64],  g_xlo[(size_t)N_NODES * 64];
__device__ __nv_bfloat16 g_m1hi[(size_t)N_NODES * 64], g_m1lo[(size_t)N_NODES * 64];
__device__ __nv_bfloat16 g_hhi[(size_t)N_NODES * 128], g_hlo[(size_t)N_NODES * 128];
__device__ __nv_bfloat16 g_m2hi[(size_t)N_NODES * 128], g_m2lo[(size_t)N_NODES * 128];
__device__ float g_hfp[(size_t)N_NODES * 128];
__device__ float g_cp1[(size_t)N_NODES * 128];
__device__ float g_cp2[(size_t)N_NODES * 128];
// weights, k-contiguous [n][k], split hi/lo
__device__ __nv_bfloat16 g_w1lhi[128 * 64],  g_w1llo[128 * 64];
__device__ __nv_bfloat16 g_w1rhi[128 * 64],  g_w1rlo[128 * 64];
__device__ __nv_bfloat16 g_w2lhi[128 * 128], g_w2llo[128 * 128];
__device__ __nv_bfloat16 g_w2rhi[128 * 128], g_w2rlo[128 * 128];

__device__ __forceinline__ void f32split(float v, __nv_bfloat16& hi, __nv_bfloat16& lo) {
    hi = __float2bfloat16(v);
    lo = __float2bfloat16(v - __bfloat162float(hi));
}

// ======================= CSR build ==========================================
__global__ void k_zero_deg() {
    int i = blockIdx.x * blockDim.x + threadIdx.x;
    if (i < N_NODES) g_deg[i] = 0;
}
__global__ void k_hist(const int* __restrict__ dst, int E) {
    int i = blockIdx.x * blockDim.x + threadIdx.x;
    if (i < E) atomicAdd(&g_deg[dst[i]], 1);
}
__global__ void k_blocksum() {
    __shared__ int sh[32];
    int i = blockIdx.x * 1024 + threadIdx.x;
    int v = (i < N_NODES) ? g_deg[i] : 0;
    #pragma unroll
    for (int d = 16; d > 0; d >>= 1) v += __shfl_down_sync(~0u, v, d);
    if ((threadIdx.x & 31) == 0) sh[threadIdx.x >> 5] = v;
    __syncthreads();
    if (threadIdx.x < 32) {
        int s = sh[threadIdx.x];
        #pragma unroll
        for (int d = 16; d > 0; d >>= 1) s += __shfl_down_sync(~0u, s, d);
        if (threadIdx.x == 0) g_bsum[blockIdx.x] = s;
    }
}
__global__ void k_scan_sums(int nb) {
    int lane = threadIdx.x;
    int carry = 0;
    for (int base = 0; base < nb; base += 32) {
        int i = base + lane;
        int orig = (i < nb) ? g_bsum[i] : 0;
        int v = orig;
        #pragma unroll
        for (int d = 1; d < 32; d <<= 1) {
            int t = __shfl_up_sync(~0u, v, d);
            if (lane >= d) v += t;
        }
        if (i < nb) g_boff[i] = carry + v - orig;
        carry += __shfl_sync(~0u, v, 31);
    }
}
__global__ void k_offsets() {
    __shared__ int sh[32];
    int tid = threadIdx.x;
    int lane = tid & 31, wid = tid >> 5;
    int i = blockIdx.x * 1024 + tid;
    int orig = (i < N_NODES) ? g_deg[i] : 0;
    int v = orig;
    #pragma unroll
    for (int d = 1; d < 32; d <<= 1) {
        int t = __shfl_up_sync(~0u, v, d);
        if (lane >= d) v += t;
    }
    if (lane == 31) sh[wid] = v;
    __syncthreads();
    if (wid == 0) {
        int s = sh[lane];
        #pragma unroll
        for (int d = 1; d < 32; d <<= 1) {
            int t = __shfl_up_sync(~0u, s, d);
            if (lane >= d) s += t;
        }
        sh[lane] = s;
    }
    __syncthreads();
    int base = g_boff[blockIdx.x] + (wid ? sh[wid - 1] : 0);
    int excl = base + v - orig;
    if (i < N_NODES) {
        g_off[i] = excl;
        g_cur[i] = excl;
        if (i == N_NODES - 1) g_off[N_NODES] = excl + orig;
    }
}
__global__ void k_scatter(const int* __restrict__ src, const int* __restrict__ dst, int E) {
    int i = blockIdx.x * blockDim.x + threadIdx.x;
    if (i < E) {
        int p = atomicAdd(&g_cur[dst[i]], 1);
        g_csr[p] = src[i];
    }
}

// ======================= prep: split x and W into bf16 hi/lo ================
__global__ void k_xsplit(const float* __restrict__ x) {
    int i = blockIdx.x * blockDim.x + threadIdx.x;   // pair index over N*32
    if (i >= N_NODES * 32) return;
    float2 v = ((const float2*)x)[i];
    __nv_bfloat162 hi, lo;
    f32split(v.x, hi.x, lo.x);
    f32split(v.y, hi.y, lo.y);
    *(__nv_bfloat162*)(g_xhi + (size_t)i * 2) = hi;
    *(__nv_bfloat162*)(g_xlo + (size_t)i * 2) = lo;
}
__global__ void k_wprep(const float* __restrict__ Wl1, const float* __restrict__ Wr1,
                        const float* __restrict__ Wl2, const float* __restrict__ Wr2) {
    int i = blockIdx.x * blockDim.x + threadIdx.x;
    if (i < 128 * 64) {
        f32split(Wl1[i], g_w1lhi[i], g_w1llo[i]);
        f32split(Wr1[i], g_w1rhi[i], g_w1rlo[i]);
    }
    if (i < 128 * 128) {
        f32split(Wl2[i], g_w2lhi[i], g_w2llo[i]);
        f32split(Wr2[i], g_w2rhi[i], g_w2rlo[i]);
    }
}

// ======================= aggregation (one warp per node) ====================
__global__ void k_agg1(const float* __restrict__ x) {
    int w = (blockIdx.x * blockDim.x + threadIdx.x) >> 5;
    int lane = threadIdx.x & 31;
    if (w >= N_NODES) return;
    int beg = g_off[w], end = g_off[w + 1];
    const float2* __restrict__ xr = (const float2*)x;
    float ax = 0.f, ay = 0.f;
    for (int base = beg; base < end; base += 32) {
        int j = base + lane;
        int s_l = (j < end) ? g_csr[j] : 0;
        int cnt = min(32, end - base);
        for (int t = 0; t < cnt; t++) {
            int s = __shfl_sync(~0u, s_l, t);
            float2 v = xr[s * 32 + lane];
            ax += v.x; ay += v.y;
        }
    }
    float inv = 1.f / fmaxf((float)(end - beg), 1.f);
    __nv_bfloat162 hi, lo;
    f32split(ax * inv, hi.x, lo.x);
    f32split(ay * inv, hi.y, lo.y);
    *(__nv_bfloat162*)(g_m1hi + (size_t)w * 64 + lane * 2) = hi;
    *(__nv_bfloat162*)(g_m1lo + (size_t)w * 64 + lane * 2) = lo;
}
__global__ void k_agg2() {
    int w = (blockIdx.x * blockDim.x + threadIdx.x) >> 5;
    int lane = threadIdx.x & 31;
    if (w >= N_NODES) return;
    int beg = g_off[w], end = g_off[w + 1];
    const float4* __restrict__ hr = (const float4*)g_hfp;   // row = 32 float4
    float a0 = 0.f, a1 = 0.f, a2 = 0.f, a3 = 0.f;
    for (int base = beg; base < end; base += 32) {
        int j = base + lane;
        int s_l = (j < end) ? g_csr[j] : 0;
        int cnt = min(32, end - base);
        for (int t = 0; t < cnt; t++) {
            int s = __shfl_sync(~0u, s_l, t);
            float4 v = hr[s * 32 + lane];
            a0 += v.x; a1 += v.y; a2 += v.z; a3 += v.w;
        }
    }
    float inv = 1.f / fmaxf((float)(end - beg), 1.f);
    __nv_bfloat162 hA, lA, hB, lB;
    f32split(a0 * inv, hA.x, lA.x);
    f32split(a1 * inv, hA.y, lA.y);
    f32split(a2 * inv, hB.x, lB.x);
    f32split(a3 * inv, hB.y, lB.y);
    *(__nv_bfloat162*)(g_m2hi + (size_t)w * 128 + lane * 4)     = hA;
    *(__nv_bfloat162*)(g_m2hi + (size_t)w * 128 + lane * 4 + 2) = hB;
    *(__nv_bfloat162*)(g_m2lo + (size_t)w * 128 + lane * 4)     = lA;
    *(__nv_bfloat162*)(g_m2lo + (size_t)w * 128 + lane * 4 + 2) = lB;
}

// ======================= mma.sync bf16x3 GEMM ===============================
// C[128 tile, 128] = A[128, KTOT] * W^T + (Cp) (+bias) (relu/h/final epilogue)
// 8 warps: warpM = wid&3 (32 rows), warpN = wid>>2 (64 cols).
// BK=64 chunks; SMEM buffer = 4 planes (Ahi, Alo, Whi, Wlo) x 128 rows x 128B,
// XOR swizzle seg' = seg ^ (row&7). Double-buffered cp.async (if >1 chunk).
#define PLANE_BYTES 16384
#define BUF_BYTES   65536

template <int KTOT>
__device__ __forceinline__ void load_chunk(
    uint32_t sbuf, const __nv_bfloat16* __restrict__ Ahi,
    const __nv_bfloat16* __restrict__ Alo, const __nv_bfloat16* __restrict__ Whi,
    const __nv_bfloat16* __restrict__ Wlo, int rowBase, int c, int tid)
{
    const __nv_bfloat16* planes[4] = {Ahi, Alo, Whi, Wlo};
    #pragma unroll
    for (int i = 0; i < 16; i++) {
        int idx = i * 256 + tid;
        int plane = idx >> 10, rem = idx & 1023;
        int row = rem >> 3, seg = rem & 7;
        uint32_t dst = sbuf + plane * PLANE_BYTES + row * 128 + ((seg ^ (row & 7)) << 4);
        int bytes = 16;
        const __nv_bfloat16* srcp;
        if (plane < 2) {
            int node = rowBase + row;
            if (node >= N_NODES) { node = N_NODES - 1; bytes = 0; }
            srcp = planes[plane] + (size_t)node * KTOT + c * 64 + seg * 8;
        } else {
            srcp = planes[plane] + (size_t)row * KTOT + c * 64 + seg * 8;
        }
        cp16(dst, srcp, bytes);
    }
}

// EPI: 0 = write raw acc to out (partial C, no bias)
//      1 = acc + Cp + bias, relu -> g_hfp (fp32) + g_hhi/g_hlo planes
//      2 = acc + Cp + bias -> out (fp32)
template <int KTOT, int EPI>
__global__ void __launch_bounds__(256, 1)
k_mmagemm(const __nv_bfloat16* __restrict__ Ahi, const __nv_bfloat16* __restrict__ Alo,
          const __nv_bfloat16* __restrict__ Whi, const __nv_bfloat16* __restrict__ Wlo,
          const float* __restrict__ bias, const float* __restrict__ Cp,
          float* __restrict__ out) {
    extern __shared__ char smem[];
    uint32_t sbase = smem_u32(smem);
    int tid = threadIdx.x;
    int wid = tid >> 5, lane = tid & 31;
    int warpM = wid & 3, warpN = wid >> 2;
    int rowBase = blockIdx.x * 128;
    constexpr int NCHUNK = KTOT / 64;

    float acc[2][8][4];
    #pragma unroll
    for (int a = 0; a < 2; a++)
        #pragma unroll
        for (int b = 0; b < 8; b++)
            #pragma unroll
            for (int d = 0; d < 4; d++) acc[a][b][d] = 0.f;

    load_chunk<KTOT>(sbase, Ahi, Alo, Whi, Wlo, rowBase, 0, tid);
    CP_COMMIT();

    for (int c = 0; c < NCHUNK; c++) {
        if (c + 1 < NCHUNK) {
            load_chunk<KTOT>(sbase + ((c + 1) & 1) * BUF_BYTES, Ahi, Alo, Whi, Wlo,
                             rowBase, c + 1, tid);
            CP_COMMIT();
            CP_WAIT(1);
        } else {
            CP_WAIT(0);
        }
        __syncthreads();

        uint32_t sb = sbase + (c & 1) * BUF_BYTES;
        uint32_t sAh = sb, sAl = sb + PLANE_BYTES;
        uint32_t sBh = sb + 2 * PLANE_BYTES, sBl = sb + 3 * PLANE_BYTES;

        #pragma unroll
        for (int ks = 0; ks < 4; ks++) {
            uint32_t aH[2][4], aL[2][4];
            #pragma unroll
            for (int tm = 0; tm < 2; tm++) {
                int row = warpM * 32 + tm * 16 + (lane & 15);
                int seg = ks * 2 + (lane >> 4);
                uint32_t off = row * 128 + ((seg ^ (row & 7)) << 4);
                ldsm_x4(aH[tm], sAh + off);
                ldsm_x4(aL[tm], sAl + off);
            }
            #pragma unroll
            for (int tp = 0; tp < 4; tp++) {
                int n = warpN * 64 + tp * 16 + (lane & 7) + (((lane >> 4) & 1) << 3);
                int seg = ks * 2 + ((lane >> 3) & 1);
                uint32_t boff = n * 128 + ((seg ^ (n & 7)) << 4);
                uint32_t bh[4];
                ldsm_x4(bh, sBh + boff);
                #pragma unroll
                for (int tm = 0; tm < 2; tm++) {
                    mma_bf16(acc[tm][tp * 2],     aH[tm], bh[0], bh[1]);
                    mma_bf16(acc[tm][tp * 2 + 1], aH[tm], bh[2], bh[3]);
                    mma_bf16(acc[tm][tp * 2],     aL[tm], bh[0], bh[1]);
                    mma_bf16(acc[tm][tp * 2 + 1], aL[tm], bh[2], bh[3]);
                }
                uint32_t bl[4];
                ldsm_x4(bl, sBl + boff);
                #pragma unroll
                for (int tm = 0; tm < 2; tm++) {
                    mma_bf16(acc[tm][tp * 2],     aH[tm], bl[0], bl[1]);
                    mma_bf16(acc[tm][tp * 2 + 1], aH[tm], bl[2], bl[3]);
                }
            }
        }
        __syncthreads();
    }

    // epilogue
    #pragma unroll
    for (int tm = 0; tm < 2; tm++) {
        #pragma unroll
        for (int tn = 0; tn < 8; tn++) {
            int col = warpN * 64 + tn * 8 + 2 * (lane & 3);
            #pragma unroll
            for (int half = 0; half < 2; half++) {
                int m = rowBase + warpM * 32 + tm * 16 + (lane >> 2) + half * 8;
                if (m >= N_NODES) continue;
                float v0 = acc[tm][tn][half * 2];
                float v1 = acc[tm][tn][half * 2 + 1];
                if (EPI == 0) {
                    float2 o; o.x = v0; o.y = v1;
                    *(float2*)(out + (size_t)m * 128 + col) = o;
                } else {
                    float2 bv = *(const float2*)(bias + col);
                    float2 cp = *(const float2*)(Cp + (size_t)m * 128 + col);
                    v0 += bv.x + cp.x;
                    v1 += bv.y + cp.y;
                    if (EPI == 1) {
                        v0 = fmaxf(v0, 0.f);
                        v1 = fmaxf(v1, 0.f);
                        float2 o; o.x = v0; o.y = v1;
                        *(float2*)(g_hfp + (size_t)m * 128 + col) = o;
                        __nv_bfloat162 hi, lo;
                        f32split(v0, hi.x, lo.x);
                        f32split(v1, hi.y, lo.y);
                        *(__nv_bfloat162*)(g_hhi + (size_t)m * 128 + col) = hi;
                        *(__nv_bfloat162*)(g_hlo + (size_t)m * 128 + col) = lo;
                    } else {
                        float2 o; o.x = v0; o.y = v1;
                        *(float2*)(out + (size_t)m * 128 + col) = o;
                    }
                }
            }
        }
    }
}

// ======================= launch =============================================
extern "C" void kernel_launch(void* const* d_in, const int* in_sizes, int n_in,
                              void* d_out, int out_size) {
    const float* x   = (const float*)d_in[0];
    const int*   ei  = (const int*)d_in[1];
    const float* Wl1 = (const float*)d_in[2];
    const float* bl1 = (const float*)d_in[3];
    const float* Wr1 = (const float*)d_in[4];
    const float* Wl2 = (const float*)d_in[5];
    const float* bl2 = (const float*)d_in[6];
    const float* Wr2 = (const float*)d_in[7];
    float* out = (float*)d_out;

    int E = in_sizes[1] / 2;
    const int* src = ei;
    const int* dst = ei + E;

    static cudaStream_t s_aux = (cudaStream_t)0;
    static cudaEvent_t ev0 = nullptr, ev1 = nullptr, ev2 = nullptr, ev3 = nullptr;
    static bool init_done = false;
    if (!init_done) {
        if (cudaStreamCreateWithFlags(&s_aux, cudaStreamNonBlocking) != cudaSuccess)
            s_aux = (cudaStream_t)0;
        cudaEventCreateWithFlags(&ev0, cudaEventDisableTiming);
        cudaEventCreateWithFlags(&ev1, cudaEventDisableTiming);
        cudaEventCreateWithFlags(&ev2, cudaEventDisableTiming);
        cudaEventCreateWithFlags(&ev3, cudaEventDisableTiming);
        cudaFuncSetAttribute((const void*)k_mmagemm<64, 0>,
                             cudaFuncAttributeMaxDynamicSharedMemorySize, BUF_BYTES);
        cudaFuncSetAttribute((const void*)k_mmagemm<64, 1>,
                             cudaFuncAttributeMaxDynamicSharedMemorySize, BUF_BYTES);
        cudaFuncSetAttribute((const void*)k_mmagemm<128, 0>,
                             cudaFuncAttributeMaxDynamicSharedMemorySize, 2 * BUF_BYTES);
        cudaFuncSetAttribute((const void*)k_mmagemm<128, 2>,
                             cudaFuncAttributeMaxDynamicSharedMemorySize, 2 * BUF_BYTES);
        init_done = true;
    }

    __nv_bfloat16 *xhi, *xlo, *m1hi, *m1lo, *hhi, *hlo, *m2hi, *m2lo;
    __nv_bfloat16 *w1lhi, *w1llo, *w1rhi, *w1rlo, *w2lhi, *w2llo, *w2rhi, *w2rlo;
    float *cp1, *cp2;
    cudaGetSymbolAddress((void**)&xhi, g_xhi);   cudaGetSymbolAddress((void**)&xlo, g_xlo);
    cudaGetSymbolAddress((void**)&m1hi, g_m1hi); cudaGetSymbolAddress((void**)&m1lo, g_m1lo);
    cudaGetSymbolAddress((void**)&hhi, g_hhi);   cudaGetSymbolAddress((void**)&hlo, g_hlo);
    cudaGetSymbolAddress((void**)&m2hi, g_m2hi); cudaGetSymbolAddress((void**)&m2lo, g_m2lo);
    cudaGetSymbolAddress((void**)&w1lhi, g_w1lhi); cudaGetSymbolAddress((void**)&w1llo, g_w1llo);
    cudaGetSymbolAddress((void**)&w1rhi, g_w1rhi); cudaGetSymbolAddress((void**)&w1rlo, g_w1rlo);
    cudaGetSymbolAddress((void**)&w2lhi, g_w2lhi); cudaGetSymbolAddress((void**)&w2llo, g_w2llo);
    cudaGetSymbolAddress((void**)&w2rhi, g_w2rhi); cudaGetSymbolAddress((void**)&w2rlo, g_w2rlo);
    cudaGetSymbolAddress((void**)&cp1, g_cp1);   cudaGetSymbolAddress((void**)&cp2, g_cp2);

    // ---- fork: aux branch = prep + x@Wr1 (independent of CSR/agg) ----
    cudaEventRecord(ev0, 0);
    cudaStreamWaitEvent(s_aux, ev0, 0);
    k_wprep<<<(128 * 128 + 255) / 256, 256, 0, s_aux>>>(Wl1, Wr1, Wl2, Wr2);
    k_xsplit<<<(N_NODES * 32 + 255) / 256, 256, 0, s_aux>>>(x);
    k_mmagemm<64, 0><<<MTILES, 256, BUF_BYTES, s_aux>>>(
        xhi, xlo, w1rhi, w1rlo, nullptr, nullptr, cp1);
    cudaEventRecord(ev1, s_aux);

    // ---- main branch: CSR build + agg1 ----
    k_zero_deg<<<(N_NODES + 255) / 256, 256>>>();
    k_hist<<<(E + 255) / 256, 256>>>(dst, E);
    k_blocksum<<<NB, 1024>>>();
    k_scan_sums<<<1, 32>>>(NB);
    k_offsets<<<NB, 1024>>>();
    k_scatter<<<(E + 255) / 256, 256>>>(src, dst, E);
    k_agg1<<<(N_NODES * 32 + 255) / 256, 256>>>(x);

    // ---- join: G1b = mean1@Wl1 + cp1 + bias, relu -> h (fp32 + planes) ----
    cudaStreamWaitEvent((cudaStream_t)0, ev1, 0);
    k_mmagemm<64, 1><<<MTILES, 256, BUF_BYTES>>>(
        m1hi, m1lo, w1lhi, w1llo, bl1, cp1, nullptr);

    // ---- fork: G2a = h@Wr2 overlaps agg2 ----
    cudaEventRecord(ev2, 0);
    cudaStreamWaitEvent(s_aux, ev2, 0);
    k_mmagemm<128, 0><<<MTILES, 256, 2 * BUF_BYTES, s_aux>>>(
        hhi, hlo, w2rhi, w2rlo, nullptr, nullptr, cp2);
    cudaEventRecord(ev3, s_aux);

    k_agg2<<<(N_NODES * 32 + 255) / 256, 256>>>();

    // ---- join: G2b = mean2@Wl2 + cp2 + bias -> out ----
    cudaStreamWaitEvent((cudaStream_t)0, ev3, 0);
    k_mmagemm<128, 2><<<MTILES, 256, 2 * BUF_BYTES>>>(
        m2hi, m2lo, w2lhi, w2llo, bl2, cp2, out);
}

// round 9
// speedup vs baseline: 1.0335x; 1.0335x over previous
#include <cuda_runtime.h>
#include <cuda_bf16.h>
#include <cstdint>

#define N_NODES 100000
#define N_EDGES 1600000
#define NB ((N_NODES + 1023) / 1024)
#define MTILES ((N_NODES + 127) / 128)

// ======================= PTX helpers (arch-agnostic, sm_80+) ================
__device__ __forceinline__ uint32_t smem_u32(const void* p) {
    uint32_t a;
    asm("{ .reg .u64 t; cvta.to.shared.u64 t, %1; cvt.u32.u64 %0, t; }" : "=r"(a) : "l"(p));
    return a;
}
__device__ __forceinline__ void ldsm_x4(uint32_t* r, uint32_t addr) {
    asm volatile("ldmatrix.sync.aligned.m8n8.x4.shared.b16 {%0,%1,%2,%3}, [%4];"
        : "=r"(r[0]), "=r"(r[1]), "=r"(r[2]), "=r"(r[3]) : "r"(addr));
}
__device__ __forceinline__ void mma_bf16(float* c, const uint32_t* a, uint32_t b0, uint32_t b1) {
    asm volatile("mma.sync.aligned.m16n8k16.row.col.f32.bf16.bf16.f32 "
        "{%0,%1,%2,%3}, {%4,%5,%6,%7}, {%8,%9}, {%0,%1,%2,%3};"
        : "+f"(c[0]), "+f"(c[1]), "+f"(c[2]), "+f"(c[3])
        : "r"(a[0]), "r"(a[1]), "r"(a[2]), "r"(a[3]), "r"(b0), "r"(b1));
}
__device__ __forceinline__ void cp16(uint32_t dst, const void* src, int srcbytes) {
    asm volatile("cp.async.cg.shared.global [%0], [%1], 16, %2;"
                 :: "r"(dst), "l"(src), "r"(srcbytes));
}
#define CP_COMMIT() asm volatile("cp.async.commit_group;" ::: "memory")
#define CP_WAIT(n)  asm volatile("cp.async.wait_group %0;" :: "n"(n) : "memory")

// ======================= scratch globals ====================================
__device__ int g_deg[N_NODES];
__device__ int g_off[N_NODES + 1];
__device__ int g_cur[N_NODES];
__device__ int g_bsum[128];
__device__ int g_boff[128];
__device__ int g_csr[N_EDGES];
// A planes: layer1 [N][128] (cols 0-63 mean1, 64-127 x), layer2 [N][256] (0-127 mean2, 128-255 h)
__device__ __nv_bfloat16 g_a1hi[(size_t)N_NODES * 128];
__device__ __nv_bfloat16 g_a1lo[(size_t)N_NODES * 128];
__device__ __nv_bfloat16 g_a2hi[(size_t)N_NODES * 256];
__device__ __nv_bfloat16 g_a2lo[(size_t)N_NODES * 256];
// fp32 copy of h for the layer-2 gather (1 LDG.128 per lane per neighbor)
__device__ float g_hfp[(size_t)N_NODES * 128];
// weights k-contiguous per output row: w1 [n=128][k=128], w2 [n=128][k=256]
__device__ __nv_bfloat16 g_w1hi[128 * 128], g_w1lo[128 * 128];
__device__ __nv_bfloat16 g_w2hi[128 * 256], g_w2lo[128 * 256];

__device__ __forceinline__ void f32split(float v, __nv_bfloat16& hi, __nv_bfloat16& lo) {
    hi = __float2bfloat16(v);
    lo = __float2bfloat16(v - __bfloat162float(hi));
}

// ======================= CSR build ==========================================
__global__ void k_zero_deg() {
    int i = blockIdx.x * blockDim.x + threadIdx.x;
    if (i < N_NODES) g_deg[i] = 0;
}
__global__ void k_hist(const int* __restrict__ dst, int E) {
    int i = blockIdx.x * blockDim.x + threadIdx.x;
    if (i < E) atomicAdd(&g_deg[dst[i]], 1);
}
__global__ void k_blocksum() {
    __shared__ int sh[32];
    int i = blockIdx.x * 1024 + threadIdx.x;
    int v = (i < N_NODES) ? g_deg[i] : 0;
    #pragma unroll
    for (int d = 16; d > 0; d >>= 1) v += __shfl_down_sync(~0u, v, d);
    if ((threadIdx.x & 31) == 0) sh[threadIdx.x >> 5] = v;
    __syncthreads();
    if (threadIdx.x < 32) {
        int s = sh[threadIdx.x];
        #pragma unroll
        for (int d = 16; d > 0; d >>= 1) s += __shfl_down_sync(~0u, s, d);
        if (threadIdx.x == 0) g_bsum[blockIdx.x] = s;
    }
}
__global__ void k_scan_sums(int nb) {
    int lane = threadIdx.x;
    int carry = 0;
    for (int base = 0; base < nb; base += 32) {
        int i = base + lane;
        int orig = (i < nb) ? g_bsum[i] : 0;
        int v = orig;
        #pragma unroll
        for (int d = 1; d < 32; d <<= 1) {
            int t = __shfl_up_sync(~0u, v, d);
            if (lane >= d) v += t;
        }
        if (i < nb) g_boff[i] = carry + v - orig;
        carry += __shfl_sync(~0u, v, 31);
    }
}
__global__ void k_offsets() {
    __shared__ int sh[32];
    int tid = threadIdx.x;
    int lane = tid & 31, wid = tid >> 5;
    int i = blockIdx.x * 1024 + tid;
    int orig = (i < N_NODES) ? g_deg[i] : 0;
    int v = orig;
    #pragma unroll
    for (int d = 1; d < 32; d <<= 1) {
        int t = __shfl_up_sync(~0u, v, d);
        if (lane >= d) v += t;
    }
    if (lane == 31) sh[wid] = v;
    __syncthreads();
    if (wid == 0) {
        int s = sh[lane];
        #pragma unroll
        for (int d = 1; d < 32; d <<= 1) {
            int t = __shfl_up_sync(~0u, s, d);
            if (lane >= d) s += t;
        }
        sh[lane] = s;
    }
    __syncthreads();
    int base = g_boff[blockIdx.x] + (wid ? sh[wid - 1] : 0);
    int excl = base + v - orig;
    if (i < N_NODES) {
        g_off[i] = excl;
        g_cur[i] = excl;
        if (i == N_NODES - 1) g_off[N_NODES] = excl + orig;
    }
}
__global__ void k_scatter(const int* __restrict__ src, const int* __restrict__ dst, int E) {
    int i = blockIdx.x * blockDim.x + threadIdx.x;
    if (i < E) {
        int p = atomicAdd(&g_cur[dst[i]], 1);
        g_csr[p] = src[i];
    }
}

// ======================= prep: split x and W into bf16 hi/lo ================
__global__ void k_xsplit(const float* __restrict__ x) {
    int i = blockIdx.x * blockDim.x + threadIdx.x;   // pair index over N*32
    if (i >= N_NODES * 32) return;
    int node = i >> 5, kp = i & 31;
    float2 v = ((const float2*)x)[i];
    __nv_bfloat162 hi, lo;
    f32split(v.x, hi.x, lo.x);
    f32split(v.y, hi.y, lo.y);
    size_t off = (size_t)node * 128 + 64 + kp * 2;
    *(__nv_bfloat162*)(g_a1hi + off) = hi;
    *(__nv_bfloat162*)(g_a1lo + off) = lo;
}
__global__ void k_wprep(const float* __restrict__ Wl1, const float* __restrict__ Wr1,
                        const float* __restrict__ Wl2, const float* __restrict__ Wr2) {
    int i = blockIdx.x * blockDim.x + threadIdx.x;
    if (i < 128 * 128) {
        int n = i >> 7, k = i & 127;
        float v = (k < 64) ? Wl1[n * 64 + k] : Wr1[n * 64 + (k - 64)];
        f32split(v, g_w1hi[i], g_w1lo[i]);
    }
    if (i < 128 * 256) {
        int n = i >> 8, k = i & 255;
        float v = (k < 128) ? Wl2[n * 128 + k] : Wr2[n * 128 + (k - 128)];
        f32split(v, g_w2hi[i], g_w2lo[i]);
    }
}

// ======================= aggregation (one warp per node, MLP-8 gather) ======
__global__ void k_agg1(const float* __restrict__ x) {
    int w = (blockIdx.x * blockDim.x + threadIdx.x) >> 5;
    int lane = threadIdx.x & 31;
    if (w >= N_NODES) return;
    int beg = g_off[w], end = g_off[w + 1];
    const float2* __restrict__ xr = (const float2*)x;
    float ax = 0.f, ay = 0.f;
    for (int base = beg; base < end; base += 32) {
        int j = base + lane;
        int s_l = (j < end) ? g_csr[j] : 0;
        int cnt = min(32, end - base);
        int t = 0;
        for (; t + 8 <= cnt; t += 8) {
            float2 v[8];
            #pragma unroll
            for (int u = 0; u < 8; u++)
                v[u] = xr[__shfl_sync(~0u, s_l, t + u) * 32 + lane];
            #pragma unroll
            for (int u = 0; u < 8; u++) { ax += v[u].x; ay += v[u].y; }
        }
        if (t + 4 <= cnt) {
            float2 v[4];
            #pragma unroll
            for (int u = 0; u < 4; u++)
                v[u] = xr[__shfl_sync(~0u, s_l, t + u) * 32 + lane];
            #pragma unroll
            for (int u = 0; u < 4; u++) { ax += v[u].x; ay += v[u].y; }
            t += 4;
        }
        for (; t < cnt; t++) {
            float2 v = xr[__shfl_sync(~0u, s_l, t) * 32 + lane];
            ax += v.x; ay += v.y;
        }
    }
    float inv = 1.f / fmaxf((float)(end - beg), 1.f);
    __nv_bfloat162 hi, lo;
    f32split(ax * inv, hi.x, lo.x);
    f32split(ay * inv, hi.y, lo.y);
    ((__nv_bfloat162*)(g_a1hi + (size_t)w * 128))[lane] = hi;
    ((__nv_bfloat162*)(g_a1lo + (size_t)w * 128))[lane] = lo;
}
__global__ void k_agg2() {
    int w = (blockIdx.x * blockDim.x + threadIdx.x) >> 5;
    int lane = threadIdx.x & 31;
    if (w >= N_NODES) return;
    int beg = g_off[w], end = g_off[w + 1];
    const float4* __restrict__ hr = (const float4*)g_hfp;   // row = 32 float4
    float a0 = 0.f, a1 = 0.f, a2 = 0.f, a3 = 0.f;
    for (int base = beg; base < end; base += 32) {
        int j = base + lane;
        int s_l = (j < end) ? g_csr[j] : 0;
        int cnt = min(32, end - base);
        int t = 0;
        for (; t + 8 <= cnt; t += 8) {
            float4 v[8];
            #pragma unroll
            for (int u = 0; u < 8; u++)
                v[u] = hr[__shfl_sync(~0u, s_l, t + u) * 32 + lane];
            #pragma unroll
            for (int u = 0; u < 8; u++) {
                a0 += v[u].x; a1 += v[u].y; a2 += v[u].z; a3 += v[u].w;
            }
        }
        if (t + 4 <= cnt) {
            float4 v[4];
            #pragma unroll
            for (int u = 0; u < 4; u++)
                v[u] = hr[__shfl_sync(~0u, s_l, t + u) * 32 + lane];
            #pragma unroll
            for (int u = 0; u < 4; u++) {
                a0 += v[u].x; a1 += v[u].y; a2 += v[u].z; a3 += v[u].w;
            }
            t += 4;
        }
        for (; t < cnt; t++) {
            float4 v = hr[__shfl_sync(~0u, s_l, t) * 32 + lane];
            a0 += v.x; a1 += v.y; a2 += v.z; a3 += v.w;
        }
    }
    float inv = 1.f / fmaxf((float)(end - beg), 1.f);
    __nv_bfloat162 hA, lA, hB, lB;
    f32split(a0 * inv, hA.x, lA.x);
    f32split(a1 * inv, hA.y, lA.y);
    f32split(a2 * inv, hB.x, lB.x);
    f32split(a3 * inv, hB.y, lB.y);
    __nv_bfloat162* oh = (__nv_bfloat162*)(g_a2hi + (size_t)w * 256);
    __nv_bfloat162* ol = (__nv_bfloat162*)(g_a2lo + (size_t)w * 256);
    oh[lane * 2] = hA; oh[lane * 2 + 1] = hB;
    ol[lane * 2] = lA; ol[lane * 2 + 1] = lB;
}

// ======================= mma.sync bf16x3 GEMM ===============================
// C[128 tile, 128] = A[128, KTOT] * W^T (W stored [n][k] k-contig).
// 8 warps: warpM = wid&3 (32 rows), warpN = wid>>2 (64 cols).
// BK=64 chunks; SMEM buffer = 4 planes (Ahi, Alo, Whi, Wlo) x 128 rows x 128B,
// XOR swizzle seg' = seg ^ (row&7). Double-buffered cp.async.
#define PLANE_BYTES 16384
#define BUF_BYTES   65536
#define GEMM_SMEM  (2 * BUF_BYTES)

template <int KTOT>
__device__ __forceinline__ void load_chunk(
    uint32_t sbuf, const __nv_bfloat16* __restrict__ Ahi,
    const __nv_bfloat16* __restrict__ Alo, const __nv_bfloat16* __restrict__ Whi,
    const __nv_bfloat16* __restrict__ Wlo, int rowBase, int c, int tid)
{
    const __nv_bfloat16* planes[4] = {Ahi, Alo, Whi, Wlo};
    #pragma unroll
    for (int i = 0; i < 16; i++) {
        int idx = i * 256 + tid;
        int plane = idx >> 10, rem = idx & 1023;
        int row = rem >> 3, seg = rem & 7;
        uint32_t dst = sbuf + plane * PLANE_BYTES + row * 128 + ((seg ^ (row & 7)) << 4);
        int bytes = 16;
        const __nv_bfloat16* srcp;
        if (plane < 2) {
            int node = rowBase + row;
            if (node >= N_NODES) { node = N_NODES - 1; bytes = 0; }
            srcp = planes[plane] + (size_t)node * KTOT + c * 64 + seg * 8;
        } else {
            srcp = planes[plane] + (size_t)row * KTOT + c * 64 + seg * 8;
        }
        cp16(dst, srcp, bytes);
    }
}

template <int KTOT, bool LAYER1>
__global__ void __launch_bounds__(256, 1)
k_mmagemm(const __nv_bfloat16* __restrict__ Ahi, const __nv_bfloat16* __restrict__ Alo,
          const __nv_bfloat16* __restrict__ Whi, const __nv_bfloat16* __restrict__ Wlo,
          const float* __restrict__ bias, float* __restrict__ out) {
    extern __shared__ char smem[];
    uint32_t sbase = smem_u32(smem);
    int tid = threadIdx.x;
    int wid = tid >> 5, lane = tid & 31;
    int warpM = wid & 3, warpN = wid >> 2;
    int rowBase = blockIdx.x * 128;
    constexpr int NCHUNK = KTOT / 64;

    float acc[2][8][4];
    #pragma unroll
    for (int a = 0; a < 2; a++)
        #pragma unroll
        for (int b = 0; b < 8; b++)
            #pragma unroll
            for (int d = 0; d < 4; d++) acc[a][b][d] = 0.f;

    load_chunk<KTOT>(sbase, Ahi, Alo, Whi, Wlo, rowBase, 0, tid);
    CP_COMMIT();

    for (int c = 0; c < NCHUNK; c++) {
        if (c + 1 < NCHUNK) {
            load_chunk<KTOT>(sbase + ((c + 1) & 1) * BUF_BYTES, Ahi, Alo, Whi, Wlo,
                             rowBase, c + 1, tid);
            CP_COMMIT();
            CP_WAIT(1);
        } else {
            CP_WAIT(0);
        }
        __syncthreads();

        uint32_t sb = sbase + (c & 1) * BUF_BYTES;
        uint32_t sAh = sb, sAl = sb + PLANE_BYTES;
        uint32_t sBh = sb + 2 * PLANE_BYTES, sBl = sb + 3 * PLANE_BYTES;

        #pragma unroll
        for (int ks = 0; ks < 4; ks++) {
            uint32_t aH[2][4], aL[2][4];
            #pragma unroll
            for (int tm = 0; tm < 2; tm++) {
                int row = warpM * 32 + tm * 16 + (lane & 15);
                int seg = ks * 2 + (lane >> 4);
                uint32_t off = row * 128 + ((seg ^ (row & 7)) << 4);
                ldsm_x4(aH[tm], sAh + off);
                ldsm_x4(aL[tm], sAl + off);
            }
            #pragma unroll
            for (int tp = 0; tp < 4; tp++) {
                int n = warpN * 64 + tp * 16 + (lane & 7) + (((lane >> 4) & 1) << 3);
                int seg = ks * 2 + ((lane >> 3) & 1);
                uint32_t boff = n * 128 + ((seg ^ (n & 7)) << 4);
                uint32_t bh[4];
                ldsm_x4(bh, sBh + boff);
                #pragma unroll
                for (int tm = 0; tm < 2; tm++) {
                    mma_bf16(acc[tm][tp * 2],     aH[tm], bh[0], bh[1]);
                    mma_bf16(acc[tm][tp * 2 + 1], aH[tm], bh[2], bh[3]);
                    mma_bf16(acc[tm][tp * 2],     aL[tm], bh[0], bh[1]);
                    mma_bf16(acc[tm][tp * 2 + 1], aL[tm], bh[2], bh[3]);
                }
                uint32_t bl[4];
                ldsm_x4(bl, sBl + boff);
                #pragma unroll
                for (int tm = 0; tm < 2; tm++) {
                    mma_bf16(acc[tm][tp * 2],     aH[tm], bl[0], bl[1]);
                    mma_bf16(acc[tm][tp * 2 + 1], aH[tm], bl[2], bl[3]);
                }
            }
        }
        __syncthreads();
    }

    // epilogue
    #pragma unroll
    for (int tm = 0; tm < 2; tm++) {
        #pragma unroll
        for (int tn = 0; tn < 8; tn++) {
            int col = warpN * 64 + tn * 8 + 2 * (lane & 3);
            float2 bv = *(const float2*)(bias + col);
            #pragma unroll
            for (int half = 0; half < 2; half++) {
                int m = rowBase + warpM * 32 + tm * 16 + (lane >> 2) + half * 8;
                if (m >= N_NODES) continue;
                float v0 = acc[tm][tn][half * 2]     + bv.x;
                float v1 = acc[tm][tn][half * 2 + 1] + bv.y;
                if (LAYER1) {
                    v0 = fmaxf(v0, 0.f);
                    v1 = fmaxf(v1, 0.f);
                    float2 o; o.x = v0; o.y = v1;
                    *(float2*)(g_hfp + (size_t)m * 128 + col) = o;
                    __nv_bfloat162 hi, lo;
                    f32split(v0, hi.x, lo.x);
                    f32split(v1, hi.y, lo.y);
                    *(__nv_bfloat162*)(g_a2hi + (size_t)m * 256 + 128 + col) = hi;
                    *(__nv_bfloat162*)(g_a2lo + (size_t)m * 256 + 128 + col) = lo;
                } else {
                    float2 o; o.x = v0; o.y = v1;
                    *(float2*)(out + (size_t)m * 128 + col) = o;
                }
            }
        }
    }
}

// ======================= launch =============================================
extern "C" void kernel_launch(void* const* d_in, const int* in_sizes, int n_in,
                              void* d_out, int out_size) {
    const float* x   = (const float*)d_in[0];
    const int*   ei  = (const int*)d_in[1];
    const float* Wl1 = (const float*)d_in[2];
    const float* bl1 = (const float*)d_in[3];
    const float* Wr1 = (const float*)d_in[4];
    const float* Wl2 = (const float*)d_in[5];
    const float* bl2 = (const float*)d_in[6];
    const float* Wr2 = (const float*)d_in[7];
    float* out = (float*)d_out;

    int E = in_sizes[1] / 2;
    const int* src = ei;
    const int* dst = ei + E;

    __nv_bfloat16 *a1hi, *a1lo, *a2hi, *a2lo, *w1hi, *w1lo, *w2hi, *w2lo;
    cudaGetSymbolAddress((void**)&a1hi, g_a1hi);
    cudaGetSymbolAddress((void**)&a1lo, g_a1lo);
    cudaGetSymbolAddress((void**)&a2hi, g_a2hi);
    cudaGetSymbolAddress((void**)&a2lo, g_a2lo);
    cudaGetSymbolAddress((void**)&w1hi, g_w1hi);
    cudaGetSymbolAddress((void**)&w1lo, g_w1lo);
    cudaGetSymbolAddress((void**)&w2hi, g_w2hi);
    cudaGetSymbolAddress((void**)&w2lo, g_w2lo);

    cudaFuncSetAttribute((const void*)k_mmagemm<128, true>,
                         cudaFuncAttributeMaxDynamicSharedMemorySize, GEMM_SMEM);
    cudaFuncSetAttribute((const void*)k_mmagemm<256, false>,
                         cudaFuncAttributeMaxDynamicSharedMemorySize, GEMM_SMEM);

    // CSR build
    k_zero_deg<<<(N_NODES + 255) / 256, 256>>>();
    k_hist<<<(E + 255) / 256, 256>>>(dst, E);
    k_blocksum<<<NB, 1024>>>();
    k_scan_sums<<<1, 32>>>(NB);
    k_offsets<<<NB, 1024>>>();
    k_scatter<<<(E + 255) / 256, 256>>>(src, dst, E);

    // operand prep
    k_wprep<<<(128 * 256 + 255) / 256, 256>>>(Wl1, Wr1, Wl2, Wr2);
    k_xsplit<<<(N_NODES * 32 + 255) / 256, 256>>>(x);

    // layer 1
    k_agg1<<<(N_NODES * 32 + 255) / 256, 256>>>(x);
    k_mmagemm<128, true><<<MTILES, 256, GEMM_SMEM>>>(a1hi, a1lo, w1hi, w1lo, bl1, nullptr);

    // layer 2
    k_agg2<<<(N_NODES * 32 + 255) / 256, 256>>>();
    k_mmagemm<256, false><<<MTILES, 256, GEMM_SMEM>>>(a2hi, a2lo, w2hi, w2lo, bl2, out);
}

// round 11
// speedup vs baseline: 1.2460x; 1.2056x over previous
#include <cuda_runtime.h>
#include <cuda_fp16.h>
#include <cstdint>

#define N_NODES 100000
#define N_EDGES 1600000
#define NB ((N_NODES + 1023) / 1024)
#define MTILES ((N_NODES + 127) / 128)

// ======================= PTX helpers (arch-agnostic, sm_80+) ================
__device__ __forceinline__ uint32_t smem_u32(const void* p) {
    uint32_t a;
    asm("{ .reg .u64 t; cvta.to.shared.u64 t, %1; cvt.u32.u64 %0, t; }" : "=r"(a) : "l"(p));
    return a;
}
__device__ __forceinline__ void ldsm_x4(uint32_t* r, uint32_t addr) {
    asm volatile("ldmatrix.sync.aligned.m8n8.x4.shared.b16 {%0,%1,%2,%3}, [%4];"
        : "=r"(r[0]), "=r"(r[1]), "=r"(r[2]), "=r"(r[3]) : "r"(addr));
}
__device__ __forceinline__ void mma_f16(float* c, const uint32_t* a, uint32_t b0, uint32_t b1) {
    asm volatile("mma.sync.aligned.m16n8k16.row.col.f32.f16.f16.f32 "
        "{%0,%1,%2,%3}, {%4,%5,%6,%7}, {%8,%9}, {%0,%1,%2,%3};"
        : "+f"(c[0]), "+f"(c[1]), "+f"(c[2]), "+f"(c[3])
        : "r"(a[0]), "r"(a[1]), "r"(a[2]), "r"(a[3]), "r"(b0), "r"(b1));
}
__device__ __forceinline__ void cp16(uint32_t dst, const void* src, int srcbytes) {
    asm volatile("cp.async.cg.shared.global [%0], [%1], 16, %2;"
                 :: "r"(dst), "l"(src), "r"(srcbytes));
}
#define CP_COMMIT() asm volatile("cp.async.commit_group;" ::: "memory")
#define CP_WAIT(n)  asm volatile("cp.async.wait_group %0;" :: "n"(n) : "memory")

// ======================= scratch globals ====================================
__device__ int g_deg[N_NODES];
__device__ int g_off[N_NODES + 1];
__device__ int g_cur[N_NODES];
__device__ int g_bsum[128];
__device__ int g_boff[128];
__device__ int g_csr[N_EDGES];
// fp16 operand tables:
// layer1 A: [N][128], cols 0-63 = mean1, cols 64-127 = x
// layer2 A: [N][256], cols 0-127 = mean2, cols 128-255 = h
__device__ __half g_a1[(size_t)N_NODES * 128];
__device__ __half g_a2[(size_t)N_NODES * 256];
// weights k-contiguous per output row: w1 [n=128][k=128], w2 [n=128][k=256]
__device__ __half g_w1[128 * 128];
__device__ __half g_w2[128 * 256];

// ======================= CSR build ==========================================
__global__ void k_zero_deg() {
    int i = blockIdx.x * blockDim.x + threadIdx.x;
    if (i < N_NODES) g_deg[i] = 0;
}
__global__ void k_hist(const int* __restrict__ dst, int E) {
    int i = blockIdx.x * blockDim.x + threadIdx.x;
    if (i < E) atomicAdd(&g_deg[dst[i]], 1);
}
__global__ void k_blocksum() {
    __shared__ int sh[32];
    int i = blockIdx.x * 1024 + threadIdx.x;
    int v = (i < N_NODES) ? g_deg[i] : 0;
    #pragma unroll
    for (int d = 16; d > 0; d >>= 1) v += __shfl_down_sync(~0u, v, d);
    if ((threadIdx.x & 31) == 0) sh[threadIdx.x >> 5] = v;
    __syncthreads();
    if (threadIdx.x < 32) {
        int s = sh[threadIdx.x];
        #pragma unroll
        for (int d = 16; d > 0; d >>= 1) s += __shfl_down_sync(~0u, s, d);
        if (threadIdx.x == 0) g_bsum[blockIdx.x] = s;
    }
}
__global__ void k_scan_sums(int nb) {
    int lane = threadIdx.x;
    int carry = 0;
    for (int base = 0; base < nb; base += 32) {
        int i = base + lane;
        int orig = (i < nb) ? g_bsum[i] : 0;
        int v = orig;
        #pragma unroll
        for (int d = 1; d < 32; d <<= 1) {
            int t = __shfl_up_sync(~0u, v, d);
            if (lane >= d) v += t;
        }
        if (i < nb) g_boff[i] = carry + v - orig;
        carry += __shfl_sync(~0u, v, 31);
    }
}
__global__ void k_offsets() {
    __shared__ int sh[32];
    int tid = threadIdx.x;
    int lane = tid & 31, wid = tid >> 5;
    int i = blockIdx.x * 1024 + tid;
    int orig = (i < N_NODES) ? g_deg[i] : 0;
    int v = orig;
    #pragma unroll
    for (int d = 1; d < 32; d <<= 1) {
        int t = __shfl_up_sync(~0u, v, d);
        if (lane >= d) v += t;
    }
    if (lane == 31) sh[wid] = v;
    __syncthreads();
    if (wid == 0) {
        int s = sh[lane];
        #pragma unroll
        for (int d = 1; d < 32; d <<= 1) {
            int t = __shfl_up_sync(~0u, s, d);
            if (lane >= d) s += t;
        }
        sh[lane] = s;
    }
    __syncthreads();
    int base = g_boff[blockIdx.x] + (wid ? sh[wid - 1] : 0);
    int excl = base + v - orig;
    if (i < N_NODES) {
        g_off[i] = excl;
        g_cur[i] = excl;
        if (i == N_NODES - 1) g_off[N_NODES] = excl + orig;
    }
}
__global__ void k_scatter(const int* __restrict__ src, const int* __restrict__ dst, int E) {
    int i = blockIdx.x * blockDim.x + threadIdx.x;
    if (i < E) {
        int p = atomicAdd(&g_cur[dst[i]], 1);
        g_csr[p] = src[i];
    }
}

// ======================= prep: x and W to fp16 ==============================
__global__ void k_xsplit(const float* __restrict__ x) {
    int i = blockIdx.x * blockDim.x + threadIdx.x;   // float2 index over N*32
    if (i >= N_NODES * 32) return;
    int node = i >> 5, kp = i & 31;
    float2 v = ((const float2*)x)[i];
    *(__half2*)(g_a1 + (size_t)node * 128 + 64 + kp * 2) = __floats2half2_rn(v.x, v.y);
}
__global__ void k_wprep(const float* __restrict__ Wl1, const float* __restrict__ Wr1,
                        const float* __restrict__ Wl2, const float* __restrict__ Wr2) {
    int i = blockIdx.x * blockDim.x + threadIdx.x;
    if (i < 128 * 128) {
        int n = i >> 7, k = i & 127;
        float v = (k < 64) ? Wl1[n * 64 + k] : Wr1[n * 64 + (k - 64)];
        g_w1[i] = __float2half_rn(v);
    }
    if (i < 128 * 256) {
        int n = i >> 8, k = i & 255;
        float v = (k < 128) ? Wl2[n * 128 + k] : Wr2[n * 128 + (k - 128)];
        g_w2[i] = __float2half_rn(v);
    }
}

// ======================= aggregation (one warp per node, fp16 gather) =======
__global__ void k_agg1() {
    int w = (blockIdx.x * blockDim.x + threadIdx.x) >> 5;
    int lane = threadIdx.x & 31;
    if (w >= N_NODES) return;
    int beg = g_off[w], end = g_off[w + 1];
    float ax = 0.f, ay = 0.f;
    for (int base = beg; base < end; base += 32) {
        int j = base + lane;
        int s_l = (j < end) ? g_csr[j] : 0;
        int cnt = min(32, end - base);
        for (int t = 0; t < cnt; t++) {
            int s = __shfl_sync(~0u, s_l, t);
            __half2 v = *(const __half2*)(g_a1 + (size_t)s * 128 + 64 + lane * 2);
            float2 f = __half22float2(v);
            ax += f.x; ay += f.y;
        }
    }
    float inv = 1.f / fmaxf((float)(end - beg), 1.f);
    *(__half2*)(g_a1 + (size_t)w * 128 + lane * 2) = __floats2half2_rn(ax * inv, ay * inv);
}
__global__ void k_agg2() {
    int w = (blockIdx.x * blockDim.x + threadIdx.x) >> 5;
    int lane = threadIdx.x & 31;
    if (w >= N_NODES) return;
    int beg = g_off[w], end = g_off[w + 1];
    float a0 = 0.f, a1 = 0.f, a2 = 0.f, a3 = 0.f;
    for (int base = beg; base < end; base += 32) {
        int j = base + lane;
        int s_l = (j < end) ? g_csr[j] : 0;
        int cnt = min(32, end - base);
        for (int t = 0; t < cnt; t++) {
            int s = __shfl_sync(~0u, s_l, t);
            uint2 u = *(const uint2*)(g_a2 + (size_t)s * 256 + 128 + lane * 4);
            float2 f0 = __half22float2(*(__half2*)&u.x);
            float2 f1 = __half22float2(*(__half2*)&u.y);
            a0 += f0.x; a1 += f0.y; a2 += f1.x; a3 += f1.y;
        }
    }
    float inv = 1.f / fmaxf((float)(end - beg), 1.f);
    uint2 o;
    *(__half2*)&o.x = __floats2half2_rn(a0 * inv, a1 * inv);
    *(__half2*)&o.y = __floats2half2_rn(a2 * inv, a3 * inv);
    *(uint2*)(g_a2 + (size_t)w * 256 + lane * 4) = o;
}

// ======================= mma.sync fp16 single-pass GEMM =====================
// C[128 tile, 128] = A[128, KTOT] * W^T (W stored [n][k] k-contig), fp32 accum.
// 8 warps: warpM = wid&3 (32 rows), warpN = wid>>2 (64 cols).
// BK=64 chunks; SMEM buffer = 2 planes (A, W) x 128 rows x 128B,
// XOR swizzle seg' = seg ^ (row&7). Double-buffered cp.async.
#define PLANE_BYTES 16384
#define BUF_BYTES   32768
#define GEMM_SMEM  (2 * BUF_BYTES)

template <int KTOT>
__device__ __forceinline__ void load_chunk(
    uint32_t sbuf, const __half* __restrict__ A, const __half* __restrict__ W,
    int rowBase, int c, int tid)
{
    #pragma unroll
    for (int i = 0; i < 8; i++) {
        int idx = i * 256 + tid;
        int plane = idx >> 10, rem = idx & 1023;
        int row = rem >> 3, seg = rem & 7;
        uint32_t dst = sbuf + plane * PLANE_BYTES + row * 128 + ((seg ^ (row & 7)) << 4);
        int bytes = 16;
        const __half* srcp;
        if (plane == 0) {
            int node = rowBase + row;
            if (node >= N_NODES) { node = N_NODES - 1; bytes = 0; }
            srcp = A + (size_t)node * KTOT + c * 64 + seg * 8;
        } else {
            srcp = W + (size_t)row * KTOT + c * 64 + seg * 8;
        }
        cp16(dst, srcp, bytes);
    }
}

template <int KTOT, bool LAYER1>
__global__ void __launch_bounds__(256)
k_mmagemm(const __half* __restrict__ A, const __half* __restrict__ W,
          const float* __restrict__ bias, float* __restrict__ out) {
    extern __shared__ char smem[];
    uint32_t sbase = smem_u32(smem);
    int tid = threadIdx.x;
    int wid = tid >> 5, lane = tid & 31;
    int warpM = wid & 3, warpN = wid >> 2;
    int rowBase = blockIdx.x * 128;
    constexpr int NCHUNK = KTOT / 64;

    float acc[2][8][4];
    #pragma unroll
    for (int a = 0; a < 2; a++)
        #pragma unroll
        for (int b = 0; b < 8; b++)
            #pragma unroll
            for (int d = 0; d < 4; d++) acc[a][b][d] = 0.f;

    load_chunk<KTOT>(sbase, A, W, rowBase, 0, tid);
    CP_COMMIT();

    for (int c = 0; c < NCHUNK; c++) {
        if (c + 1 < NCHUNK) {
            load_chunk<KTOT>(sbase + ((c + 1) & 1) * BUF_BYTES, A, W, rowBase, c + 1, tid);
            CP_COMMIT();
            CP_WAIT(1);
        } else {
            CP_WAIT(0);
        }
        __syncthreads();

        uint32_t sb = sbase + (c & 1) * BUF_BYTES;
        uint32_t sA = sb, sB = sb + PLANE_BYTES;

        #pragma unroll
        for (int ks = 0; ks < 4; ks++) {
            uint32_t aF[2][4];
            #pragma unroll
            for (int tm = 0; tm < 2; tm++) {
                int row = warpM * 32 + tm * 16 + (lane & 15);
                int seg = ks * 2 + (lane >> 4);
                uint32_t off = row * 128 + ((seg ^ (row & 7)) << 4);
                ldsm_x4(aF[tm], sA + off);
            }
            #pragma unroll
            for (int tp = 0; tp < 4; tp++) {
                int n = warpN * 64 + tp * 16 + (lane & 7) + (((lane >> 4) & 1) << 3);
                int seg = ks * 2 + ((lane >> 3) & 1);
                uint32_t boff = n * 128 + ((seg ^ (n & 7)) << 4);
                uint32_t bF[4];
                ldsm_x4(bF, sB + boff);
                #pragma unroll
                for (int tm = 0; tm < 2; tm++) {
                    mma_f16(acc[tm][tp * 2],     aF[tm], bF[0], bF[1]);
                    mma_f16(acc[tm][tp * 2 + 1], aF[tm], bF[2], bF[3]);
                }
            }
        }
        __syncthreads();
    }

    // epilogue
    #pragma unroll
    for (int tm = 0; tm < 2; tm++) {
        #pragma unroll
        for (int tn = 0; tn < 8; tn++) {
            int col = warpN * 64 + tn * 8 + 2 * (lane & 3);
            float2 bv = *(const float2*)(bias + col);
            #pragma unroll
            for (int half = 0; half < 2; half++) {
                int m = rowBase + warpM * 32 + tm * 16 + (lane >> 2) + half * 8;
                if (m >= N_NODES) continue;
                float v0 = acc[tm][tn][half * 2]     + bv.x;
                float v1 = acc[tm][tn][half * 2 + 1] + bv.y;
                if (LAYER1) {
                    v0 = fmaxf(v0, 0.f);
                    v1 = fmaxf(v1, 0.f);
                    *(__half2*)(g_a2 + (size_t)m * 256 + 128 + col) = __floats2half2_rn(v0, v1);
                } else {
                    float2 o; o.x = v0; o.y = v1;
                    *(float2*)(out + (size_t)m * 128 + col) = o;
                }
            }
        }
    }
}

// ======================= launch =============================================
extern "C" void kernel_launch(void* const* d_in, const int* in_sizes, int n_in,
                              void* d_out, int out_size) {
    const float* x   = (const float*)d_in[0];
    const int*   ei  = (const int*)d_in[1];
    const float* Wl1 = (const float*)d_in[2];
    const float* bl1 = (const float*)d_in[3];
    const float* Wr1 = (const float*)d_in[4];
    const float* Wl2 = (const float*)d_in[5];
    const float* bl2 = (const float*)d_in[6];
    const float* Wr2 = (const float*)d_in[7];
    float* out = (float*)d_out;

    int E = in_sizes[1] / 2;
    const int* src = ei;
    const int* dst = ei + E;

    __half *a1, *a2, *w1, *w2;
    cudaGetSymbolAddress((void**)&a1, g_a1);
    cudaGetSymbolAddress((void**)&a2, g_a2);
    cudaGetSymbolAddress((void**)&w1, g_w1);
    cudaGetSymbolAddress((void**)&w2, g_w2);

    cudaFuncSetAttribute((const void*)k_mmagemm<128, true>,
                         cudaFuncAttributeMaxDynamicSharedMemorySize, GEMM_SMEM);
    cudaFuncSetAttribute((const void*)k_mmagemm<256, false>,
                         cudaFuncAttributeMaxDynamicSharedMemorySize, GEMM_SMEM);

    // CSR build
    k_zero_deg<<<(N_NODES + 255) / 256, 256>>>();
    k_hist<<<(E + 255) / 256, 256>>>(dst, E);
    k_blocksum<<<NB, 1024>>>();
    k_scan_sums<<<1, 32>>>(NB);
    k_offsets<<<NB, 1024>>>();
    k_scatter<<<(E + 255) / 256, 256>>>(src, dst, E);

    // operand prep
    k_wprep<<<(128 * 256 + 255) / 256, 256>>>(Wl1, Wr1, Wl2, Wr2);
    k_xsplit<<<(N_NODES * 32 + 255) / 256, 256>>>(x);

    // layer 1
    k_agg1<<<(N_NODES * 32 + 255) / 256, 256>>>();
    k_mmagemm<128, true><<<MTILES, 256, GEMM_SMEM>>>(a1, w1, bl1, nullptr);

    // layer 2
    k_agg2<<<(N_NODES * 32 + 255) / 256, 256>>>();
    k_mmagemm<256, false><<<MTILES, 256, GEMM_SMEM>>>(a2, w2, bl2, out);
}

// round 13
// speedup vs baseline: 1.8401x; 1.4769x over previous
#include <cuda_runtime.h>
#include <cuda_fp16.h>
#include <cstdint>

#define N_NODES 100000
#define N_EDGES 1600000
#define NB ((N_NODES + 1023) / 1024)
#define MTILES ((N_NODES + 127) / 128)

// ======================= PTX helpers (arch-agnostic, sm_80+) ================
__device__ __forceinline__ uint32_t smem_u32(const void* p) {
    uint32_t a;
    asm("{ .reg .u64 t; cvta.to.shared.u64 t, %1; cvt.u32.u64 %0, t; }" : "=r"(a) : "l"(p));
    return a;
}
__device__ __forceinline__ void ldsm_x4(uint32_t* r, uint32_t addr) {
    asm volatile("ldmatrix.sync.aligned.m8n8.x4.shared.b16 {%0,%1,%2,%3}, [%4];"
        : "=r"(r[0]), "=r"(r[1]), "=r"(r[2]), "=r"(r[3]) : "r"(addr));
}
__device__ __forceinline__ void mma_f16(float* c, const uint32_t* a, uint32_t b0, uint32_t b1) {
    asm volatile("mma.sync.aligned.m16n8k16.row.col.f32.f16.f16.f32 "
        "{%0,%1,%2,%3}, {%4,%5,%6,%7}, {%8,%9}, {%0,%1,%2,%3};"
        : "+f"(c[0]), "+f"(c[1]), "+f"(c[2]), "+f"(c[3])
        : "r"(a[0]), "r"(a[1]), "r"(a[2]), "r"(a[3]), "r"(b0), "r"(b1));
}
__device__ __forceinline__ void cp16(uint32_t dst, const void* src, int srcbytes) {
    asm volatile("cp.async.cg.shared.global [%0], [%1], 16, %2;"
                 :: "r"(dst), "l"(src), "r"(srcbytes));
}
#define CP_COMMIT() asm volatile("cp.async.commit_group;" ::: "memory")
#define CP_WAIT(n)  asm volatile("cp.async.wait_group %0;" :: "n"(n) : "memory")

// ======================= scratch globals ====================================
__device__ int g_deg[N_NODES];        // zero at load; re-zeroed by k_scatter each run
__device__ int g_off[N_NODES + 1];
__device__ int g_cur[N_NODES];
__device__ int g_csr[N_EDGES];
// fp16 operand tables:
// layer1 A: [N][128], cols 0-63 = mean1, cols 64-127 = x
// layer2 A: [N][256], cols 0-127 = mean2, cols 128-255 = h
__device__ __half g_a1[(size_t)N_NODES * 128];
__device__ __half g_a2[(size_t)N_NODES * 256];
// weights k-contiguous per output row: w1 [n=128][k=128], w2 [n=128][k=256]
__device__ __half g_w1[128 * 128];
__device__ __half g_w2[128 * 256];

// ======================= fused hist + operand prep ==========================
__global__ void k_hist_prep(const int* __restrict__ dst, int E,
                            const float* __restrict__ x,
                            const float* __restrict__ Wl1, const float* __restrict__ Wr1,
                            const float* __restrict__ Wl2, const float* __restrict__ Wr2) {
    int i = blockIdx.x * blockDim.x + threadIdx.x;
    int total = gridDim.x * blockDim.x;
    if (i < E) atomicAdd(&g_deg[dst[i]], 1);
    // x -> fp16 (float2 granules, N*32 of them)
    for (int j = i; j < N_NODES * 32; j += total) {
        int node = j >> 5, kp = j & 31;
        float2 v = ((const float2*)x)[j];
        *(__half2*)(g_a1 + (size_t)node * 128 + 64 + kp * 2) = __floats2half2_rn(v.x, v.y);
    }
    // weights -> fp16, k-concat layout
    if (i < 128 * 128) {
        int n = i >> 7, k = i & 127;
        float v = (k < 64) ? Wl1[n * 64 + k] : Wr1[n * 64 + (k - 64)];
        g_w1[i] = __float2half_rn(v);
    }
    if (i < 128 * 256) {
        int n = i >> 8, k = i & 255;
        float v = (k < 128) ? Wl2[n * 128 + k] : Wr2[n * 128 + (k - 128)];
        g_w2[i] = __float2half_rn(v);
    }
}

// ======================= offsets: per-block independent prefix ==============
// Each block sums g_deg[0 .. bid*1024) itself (parallel redundant reads, no
// cross-kernel scan chain), then scans its own 1024 degrees.
__global__ void k_offsets() {
    __shared__ int sh[32];
    __shared__ int s_pre;
    int tid = threadIdx.x;
    int lane = tid & 31, wid = tid >> 5;
    int limit = blockIdx.x * 1024;

    // predecessor prefix
    int pre = 0;
    for (int j = tid; j < limit; j += 1024) pre += g_deg[j];
    #pragma unroll
    for (int d = 16; d > 0; d >>= 1) pre += __shfl_down_sync(~0u, pre, d);
    if (lane == 0) sh[wid] = pre;
    __syncthreads();
    if (wid == 0) {
        int s = sh[lane];
        #pragma unroll
        for (int d = 16; d > 0; d >>= 1) s += __shfl_down_sync(~0u, s, d);
        if (lane == 0) s_pre = s;
    }
    __syncthreads();

    // own-block scan
    int i = limit + tid;
    int orig = (i < N_NODES) ? g_deg[i] : 0;
    int v = orig;
    #pragma unroll
    for (int d = 1; d < 32; d <<= 1) {
        int t = __shfl_up_sync(~0u, v, d);
        if (lane >= d) v += t;
    }
    if (lane == 31) sh[wid] = v;
    __syncthreads();
    if (wid == 0) {
        int s = sh[lane];
        #pragma unroll
        for (int d = 1; d < 32; d <<= 1) {
            int t = __shfl_up_sync(~0u, s, d);
            if (lane >= d) s += t;
        }
        sh[lane] = s;
    }
    __syncthreads();
    int base = s_pre + (wid ? sh[wid - 1] : 0);
    int excl = base + v - orig;
    if (i < N_NODES) {
        g_off[i] = excl;
        g_cur[i] = excl;
        if (i == N_NODES - 1) g_off[N_NODES] = excl + orig;
    }
}

__global__ void k_scatter(const int* __restrict__ src, const int* __restrict__ dst, int E) {
    int i = blockIdx.x * blockDim.x + threadIdx.x;
    if (i < E) {
        int p = atomicAdd(&g_cur[dst[i]], 1);
        g_csr[p] = src[i];
    }
    if (i < N_NODES) g_deg[i] = 0;   // restore invariant for next graph replay
}

// ======================= aggregation (one warp per node, fp16 gather) =======
__global__ void k_agg1() {
    int w = (blockIdx.x * blockDim.x + threadIdx.x) >> 5;
    int lane = threadIdx.x & 31;
    if (w >= N_NODES) return;
    int beg = g_off[w], end = g_off[w + 1];
    float ax = 0.f, ay = 0.f;
    for (int base = beg; base < end; base += 32) {
        int j = base + lane;
        int s_l = (j < end) ? g_csr[j] : 0;
        int cnt = min(32, end - base);
        for (int t = 0; t < cnt; t++) {
            int s = __shfl_sync(~0u, s_l, t);
            __half2 v = *(const __half2*)(g_a1 + (size_t)s * 128 + 64 + lane * 2);
            float2 f = __half22float2(v);
            ax += f.x; ay += f.y;
        }
    }
    float inv = 1.f / fmaxf((float)(end - beg), 1.f);
    *(__half2*)(g_a1 + (size_t)w * 128 + lane * 2) = __floats2half2_rn(ax * inv, ay * inv);
}
__global__ void k_agg2() {
    int w = (blockIdx.x * blockDim.x + threadIdx.x) >> 5;
    int lane = threadIdx.x & 31;
    if (w >= N_NODES) return;
    int beg = g_off[w], end = g_off[w + 1];
    float a0 = 0.f, a1 = 0.f, a2 = 0.f, a3 = 0.f;
    for (int base = beg; base < end; base += 32) {
        int j = base + lane;
        int s_l = (j < end) ? g_csr[j] : 0;
        int cnt = min(32, end - base);
        for (int t = 0; t < cnt; t++) {
            int s = __shfl_sync(~0u, s_l, t);
            uint2 u = *(const uint2*)(g_a2 + (size_t)s * 256 + 128 + lane * 4);
            float2 f0 = __half22float2(*(__half2*)&u.x);
            float2 f1 = __half22float2(*(__half2*)&u.y);
            a0 += f0.x; a1 += f0.y; a2 += f1.x; a3 += f1.y;
        }
    }
    float inv = 1.f / fmaxf((float)(end - beg), 1.f);
    uint2 o;
    *(__half2*)&o.x = __floats2half2_rn(a0 * inv, a1 * inv);
    *(__half2*)&o.y = __floats2half2_rn(a2 * inv, a3 * inv);
    *(uint2*)(g_a2 + (size_t)w * 256 + lane * 4) = o;
}

// ======================= mma.sync fp16 single-pass GEMM =====================
#define PLANE_BYTES 16384
#define BUF_BYTES   32768
#define GEMM_SMEM  (2 * BUF_BYTES)

template <int KTOT>
__device__ __forceinline__ void load_chunk(
    uint32_t sbuf, const __half* __restrict__ A, const __half* __restrict__ W,
    int rowBase, int c, int tid)
{
    #pragma unroll
    for (int i = 0; i < 8; i++) {
        int idx = i * 256 + tid;
        int plane = idx >> 10, rem = idx & 1023;
        int row = rem >> 3, seg = rem & 7;
        uint32_t dst = sbuf + plane * PLANE_BYTES + row * 128 + ((seg ^ (row & 7)) << 4);
        int bytes = 16;
        const __half* srcp;
        if (plane == 0) {
            int node = rowBase + row;
            if (node >= N_NODES) { node = N_NODES - 1; bytes = 0; }
            srcp = A + (size_t)node * KTOT + c * 64 + seg * 8;
        } else {
            srcp = W + (size_t)row * KTOT + c * 64 + seg * 8;
        }
        cp16(dst, srcp, bytes);
    }
}

template <int KTOT, bool LAYER1>
__global__ void __launch_bounds__(256)
k_mmagemm(const __half* __restrict__ A, const __half* __restrict__ W,
          const float* __restrict__ bias, float* __restrict__ out) {
    extern __shared__ char smem[];
    uint32_t sbase = smem_u32(smem);
    int tid = threadIdx.x;
    int wid = tid >> 5, lane = tid & 31;
    int warpM = wid & 3, warpN = wid >> 2;
    int rowBase = blockIdx.x * 128;
    constexpr int NCHUNK = KTOT / 64;

    float acc[2][8][4];
    #pragma unroll
    for (int a = 0; a < 2; a++)
        #pragma unroll
        for (int b = 0; b < 8; b++)
            #pragma unroll
            for (int d = 0; d < 4; d++) acc[a][b][d] = 0.f;

    load_chunk<KTOT>(sbase, A, W, rowBase, 0, tid);
    CP_COMMIT();

    for (int c = 0; c < NCHUNK; c++) {
        if (c + 1 < NCHUNK) {
            load_chunk<KTOT>(sbase + ((c + 1) & 1) * BUF_BYTES, A, W, rowBase, c + 1, tid);
            CP_COMMIT();
            CP_WAIT(1);
        } else {
            CP_WAIT(0);
        }
        __syncthreads();

        uint32_t sb = sbase + (c & 1) * BUF_BYTES;
        uint32_t sA = sb, sB = sb + PLANE_BYTES;

        #pragma unroll
        for (int ks = 0; ks < 4; ks++) {
            uint32_t aF[2][4];
            #pragma unroll
            for (int tm = 0; tm < 2; tm++) {
                int row = warpM * 32 + tm * 16 + (lane & 15);
                int seg = ks * 2 + (lane >> 4);
                uint32_t off = row * 128 + ((seg ^ (row & 7)) << 4);
                ldsm_x4(aF[tm], sA + off);
            }
            #pragma unroll
            for (int tp = 0; tp < 4; tp++) {
                int n = warpN * 64 + tp * 16 + (lane & 7) + (((lane >> 4) & 1) << 3);
                int seg = ks * 2 + ((lane >> 3) & 1);
                uint32_t boff = n * 128 + ((seg ^ (n & 7)) << 4);
                uint32_t bF[4];
                ldsm_x4(bF, sB + boff);
                #pragma unroll
                for (int tm = 0; tm < 2; tm++) {
                    mma_f16(acc[tm][tp * 2],     aF[tm], bF[0], bF[1]);
                    mma_f16(acc[tm][tp * 2 + 1], aF[tm], bF[2], bF[3]);
                }
            }
        }
        __syncthreads();
    }

    // epilogue
    #pragma unroll
    for (int tm = 0; tm < 2; tm++) {
        #pragma unroll
        for (int tn = 0; tn < 8; tn++) {
            int col = warpN * 64 + tn * 8 + 2 * (lane & 3);
            float2 bv = *(const float2*)(bias + col);
            #pragma unroll
            for (int half = 0; half < 2; half++) {
                int m = rowBase + warpM * 32 + tm * 16 + (lane >> 2) + half * 8;
                if (m >= N_NODES) continue;
                float v0 = acc[tm][tn][half * 2]     + bv.x;
                float v1 = acc[tm][tn][half * 2 + 1] + bv.y;
                if (LAYER1) {
                    v0 = fmaxf(v0, 0.f);
                    v1 = fmaxf(v1, 0.f);
                    *(__half2*)(g_a2 + (size_t)m * 256 + 128 + col) = __floats2half2_rn(v0, v1);
                } else {
                    float2 o; o.x = v0; o.y = v1;
                    *(float2*)(out + (size_t)m * 128 + col) = o;
                }
            }
        }
    }
}

// ======================= launch =============================================
extern "C" void kernel_launch(void* const* d_in, const int* in_sizes, int n_in,
                              void* d_out, int out_size) {
    const float* x   = (const float*)d_in[0];
    const int*   ei  = (const int*)d_in[1];
    const float* Wl1 = (const float*)d_in[2];
    const float* bl1 = (const float*)d_in[3];
    const float* Wr1 = (const float*)d_in[4];
    const float* Wl2 = (const float*)d_in[5];
    const float* bl2 = (const float*)d_in[6];
    const float* Wr2 = (const float*)d_in[7];
    float* out = (float*)d_out;

    int E = in_sizes[1] / 2;
    const int* src = ei;
    const int* dst = ei + E;

    __half *a1, *a2, *w1, *w2;
    cudaGetSymbolAddress((void**)&a1, g_a1);
    cudaGetSymbolAddress((void**)&a2, g_a2);
    cudaGetSymbolAddress((void**)&w1, g_w1);
    cudaGetSymbolAddress((void**)&w2, g_w2);

    cudaFuncSetAttribute((const void*)k_mmagemm<128, true>,
                         cudaFuncAttributeMaxDynamicSharedMemorySize, GEMM_SMEM);
    cudaFuncSetAttribute((const void*)k_mmagemm<256, false>,
                         cudaFuncAttributeMaxDynamicSharedMemorySize, GEMM_SMEM);

    // CSR build + operand prep (fused)
    k_hist_prep<<<(E + 255) / 256, 256>>>(dst, E, x, Wl1, Wr1, Wl2, Wr2);
    k_offsets<<<NB, 1024>>>();
    k_scatter<<<(E + 255) / 256, 256>>>(src, dst, E);

    // layer 1
    k_agg1<<<(N_NODES * 32 + 255) / 256, 256>>>();
    k_mmagemm<128, true><<<MTILES, 256, GEMM_SMEM>>>(a1, w1, bl1, nullptr);

    // layer 2
    k_agg2<<<(N_NODES * 32 + 255) / 256, 256>>>();
    k_mmagemm<256, false><<<MTILES, 256, GEMM_SMEM>>>(a2, w2, bl2, out);
}